// round 14
// baseline (speedup 1.0000x reference)
#include <cuda_runtime.h>
#include <math.h>

#define NB 2048
#define NC 32
#define DD 64
#define AA 8
#define AS 66   // A row stride (even -> float2-aligned rows)
#define XS 34   // X row stride (even -> float2-aligned rows)

// exp1[n][m] = -0.25 * sum_d (c_n[d]-c_m[d])^2 / l[d]^2   (batch-independent)
__device__ float g_exp1[NC * NC];

__global__ void prep_kernel(const float* __restrict__ centers,
                            const float* __restrict__ ls) {
    int t = threadIdx.x;           // 1024 threads = 32x32 pairs
    int n = t >> 5, m = t & 31;
    float acc = 0.f;
#pragma unroll
    for (int d = 0; d < DD; ++d) {
        float df = centers[n * DD + d] - centers[m * DD + d];
        float l = ls[d];
        acc += (df * df) / (l * l);
    }
    g_exp1[t] = -0.25f * acc;
}

// Blocked in-place Cholesky, panel width 8. Panel factor by one warp
// (rotating across warps), trailing SYRK by all 256 threads (float2 loads).
__device__ __forceinline__ void cholesky64_blk(float (*A)[AS], int tid) {
    const int lane = tid & 31;
    const int warp = tid >> 5;
    const int ty = tid >> 4, tx = tid & 15;
#pragma unroll 1
    for (int p = 0; p < 8; ++p) {
        const int k0 = p * 8, pe = k0 + 8;
        if (warp == (p & 7)) {
#pragma unroll 1
            for (int j = k0; j < pe; ++j) {
                float d = A[j][j];
                float inv = rsqrtf(d);
                if (lane == 0) A[j][j] = d * inv;      // sqrt(d)
                for (int i = j + 1 + lane; i < DD; i += 32) A[i][j] *= inv;
                __syncwarp();
                float cj[7];
#pragma unroll
                for (int q = 0; q < 7; ++q) {
                    int jj = j + 1 + q;
                    cj[q] = (jj < pe) ? A[jj][j] : 0.f;
                }
                for (int i = j + 1 + lane; i < DD; i += 32) {
                    float a = A[i][j];
#pragma unroll
                    for (int q = 0; q < 7; ++q) {
                        int jj = j + 1 + q;
                        if (jj < pe) A[i][jj] -= a * cj[q];
                    }
                }
                __syncwarp();
            }
        }
        __syncthreads();
        if (pe < DD) {
            for (int i = pe + ty; i < DD; i += 16) {
                float ai[8];
                const float2* ar = (const float2*)&A[i][k0];
#pragma unroll
                for (int q = 0; q < 4; ++q) {
                    float2 v = ar[q];
                    ai[2 * q] = v.x; ai[2 * q + 1] = v.y;
                }
                for (int j = pe + tx; j <= i; j += 16) {
                    float acc = A[i][j];
                    const float2* aj = (const float2*)&A[j][k0];
#pragma unroll
                    for (int q = 0; q < 4; ++q) {
                        float2 v = aj[q];
                        acc -= ai[2 * q] * v.x + ai[2 * q + 1] * v.y;
                    }
                    A[i][j] = acc;
                }
            }
            __syncthreads();
        }
    }
}

// In-place inversion of lower-triangular L (64x64) held in A (lower+diag).
// U scratch: >= 3*16*17 floats. Result: A holds Linv (lower+diag); the
// upper triangle of each 16x16 diagonal block is ZEROED (dense block GEMMs
// below require it).
__device__ __forceinline__ void invert_lower64(float (*A)[AS],
                                               float* U, int tid) {
    const int lane = tid & 31;
    const int warp = tid >> 5;
    if (warp < 4) {
        const int b0 = warp * 16;
        const int j = lane;
#pragma unroll 1
        for (int i = 0; i < 16; ++i) {
            float s = 0.f;
            if (j < i) {
                for (int k = j; k < i; ++k) s += A[b0 + i][b0 + k] * A[b0 + k][b0 + j];
            }
            float di = A[b0 + i][b0 + i];
            __syncwarp();
            if (j < i)            A[b0 + i][b0 + j] = -s / di;
            else if (j == i)      A[b0 + i][b0 + i] = 1.0f / di;
            else if (j < 16)      A[b0 + i][b0 + j] = 0.0f;   // zero upper
            __syncwarp();
        }
    }
    __syncthreads();
    const int r = tid >> 4, c = tid & 15;
#pragma unroll 1
    for (int bj = 2; bj >= 0; --bj) {
        const int nb = 3 - bj;
        for (int m = 0; m < nb; ++m) {
            const int bi = bj + 1 + m;
            float acc = 0.f;
            for (int bk = bj + 1; bk <= bi; ++bk) {
                const float2* a1 = (const float2*)&A[bi * 16 + r][bk * 16];
#pragma unroll
                for (int kk = 0; kk < 8; ++kk) {
                    float2 v = a1[kk];
                    acc += v.x * A[bk * 16 + 2 * kk][bj * 16 + c];
                    acc += v.y * A[bk * 16 + 2 * kk + 1][bj * 16 + c];
                }
            }
            U[m * 272 + r * 17 + c] = acc;
        }
        __syncthreads();
        for (int m = 0; m < nb; ++m) {
            const int bi = bj + 1 + m;
            float acc = 0.f;
#pragma unroll
            for (int kk = 0; kk < 16; ++kk)
                acc += U[m * 272 + r * 17 + kk] * A[bj * 16 + kk][bj * 16 + c];
            A[bi * 16 + r][bj * 16 + c] = -acc;
        }
        __syncthreads();
    }
}

__global__ __launch_bounds__(256, 4) void rbf_kernel(
    const float* __restrict__ mean, const float* __restrict__ cov,
    const float* __restrict__ centers, const float* __restrict__ weights,
    const float* __restrict__ ls,
    float* __restrict__ out_am, float* __restrict__ out_ac,
    float* __restrict__ out_cc) {
    __shared__ float A[DD][AS];         // matrix -> L -> Linv (both phases)
    __shared__ float X[DD][XS];         // RHS / solutions (D-major)
    __shared__ float CC[DD][AA];        // cross_cov pre-squash
    __shared__ float G[NC][NC + 1];     // scratch (inversion U) -> Gram -> Q
    __shared__ float W[NC][AA];
    __shared__ float pw[NC][AA];        // phi*W, later P = Q W
    __shared__ float phi[NC];
    __shared__ float cp[8][NC];         // column-norm partials
    __shared__ float smean[DD], sinvl[DD], sl2[DD];
    __shared__ float ldiag[DD];
    __shared__ float s_scal[2];         // [0]=normalizer, [1]=c_q
    __shared__ float s_am[AA], s_dc[AA], s_cd[AA];
    __shared__ float R8[AA][AA + 1];
    __shared__ float ACm[AA][AA + 1];
    __shared__ float gd[NC];

    const int tid = threadIdx.x;
    const int b = blockIdx.x;
    const float* covb = cov + (size_t)b * DD * DD;
    const float* meanb = mean + (size_t)b * DD;
    float* U = &G[0][0];
    const int n = tid & 31, r0 = tid >> 5;   // apply-phase mapping (r0 warp-uniform)

    if (tid < DD) {
        float l = ls[tid];
        smean[tid] = meanb[tid];
        sinvl[tid] = 1.0f / l;
        sl2[tid] = l * l;
    }
    {
        int nn = tid >> 3, a = tid & 7;
        W[nn][a] = weights[tid];
    }
    __syncthreads();

    // A = diag(invl) cov diag(invl) + I ; X[d][n] = (c_n[d]-mean[d])*invl[d]
    for (int idx = tid; idx < DD * DD; idx += 256) {
        int i = idx >> 6, j = idx & 63;
        float v = covb[idx] * sinvl[i] * sinvl[j];
        if (i == j) v += 1.0f;
        A[i][j] = v;
    }
    for (int idx = tid; idx < NC * DD; idx += 256) {
        int nn = idx >> 6, d = idx & 63;
        X[d][nn] = (centers[idx] - smean[d]) * sinvl[d];
    }
    __syncthreads();

    cholesky64_blk(A, tid);
    if (tid < DD) ldiag[tid] = logf(A[tid][tid]);
    __syncthreads();
    if (tid < 32) {   // warp-parallel logdet reduce
        float s = ldiag[tid] + ldiag[tid + 32];
#pragma unroll
        for (int o = 16; o > 0; o >>= 1) s += __shfl_down_sync(0xffffffffu, s, o);
        if (tid == 0) s_scal[0] = expf(-s);   // exp(-0.5*logdet)
    }
    invert_lower64(A, U, tid);

    // ---- Y1 = Linv * S  (block-triangular, float2 A rows), colnorms -> cp
    {
        float y[8];
#pragma unroll
        for (int u = 0; u < 8; ++u) y[u] = 0.f;
#pragma unroll
        for (int kb = 0; kb < 8; ++kb) {
            float xr[8];
#pragma unroll
            for (int q = 0; q < 8; ++q) xr[q] = X[kb * 8 + q][n];
            {   // diagonal block u == kb: k <= i, i = kb*8+r0 (warp-uniform)
                const float* ar = &A[kb * 8 + r0][kb * 8];
#pragma unroll
                for (int q = 0; q < 8; ++q)
                    if (q <= r0) y[kb] += ar[q] * xr[q];
            }
#pragma unroll
            for (int u = kb + 1; u < 8; ++u) {   // dense blocks below diag
                const float2* ar = (const float2*)&A[u * 8 + r0][kb * 8];
#pragma unroll
                for (int q = 0; q < 4; ++q) {
                    float2 v = ar[q];
                    y[u] += v.x * xr[2 * q];
                    y[u] += v.y * xr[2 * q + 1];
                }
            }
        }
        float pn = 0.f;
#pragma unroll
        for (int u = 0; u < 8; ++u) pn += y[u] * y[u];
        cp[r0][n] = pn;
        __syncthreads();                   // all reads of X done
#pragma unroll
        for (int u = 0; u < 8; ++u) X[u * 8 + r0][n] = y[u];
        __syncthreads();

        // ---- T = Linv^T * Y1 (block-triangular transpose) ----
#pragma unroll
        for (int u = 0; u < 8; ++u) y[u] = 0.f;
#pragma unroll
        for (int kb = 0; kb < 8; ++kb) {
            float xr[8];
#pragma unroll
            for (int q = 0; q < 8; ++q) xr[q] = X[kb * 8 + q][n];
            {   // diagonal block u == kb: k >= i
                const int i = kb * 8 + r0;
#pragma unroll
                for (int q = 0; q < 8; ++q)
                    if (q >= r0) y[kb] += A[kb * 8 + q][i] * xr[q];
            }
#pragma unroll
            for (int u = 0; u < kb; ++u) {   // dense blocks (k-block > i-block)
                const int i = u * 8 + r0;
#pragma unroll
                for (int q = 0; q < 8; ++q) y[u] += A[kb * 8 + q][i] * xr[q];
            }
        }
        __syncthreads();
#pragma unroll
        for (int u = 0; u < 8; ++u) X[u * 8 + r0][n] = y[u];
    }
    __syncthreads();

    // phi[n] = normalizer * exp(-0.5 * |Y1 col n|^2)   (accurate expf: tiny values)
    if (tid < NC) {
        float acc = 0.f;
#pragma unroll
        for (int u = 0; u < 8; ++u) acc += cp[u][tid];
        phi[tid] = expf(-0.5f * acc) * s_scal[0];
    }
    __syncthreads();
    {
        int nn = tid >> 3, a = tid & 7;
        pw[nn][a] = phi[nn] * W[nn][a];
    }
    __syncthreads();
    if (tid < AA) {
        float s = 0.f;
        for (int nn = 0; nn < NC; ++nn) s += pw[nn][tid];
        s_am[tid] = s;
    }
    // cross_cov[d][a] = invl[d] * sum_n t^T[d][n] * (phi W)[n][a]
    for (int idx = tid; idx < DD * AA; idx += 256) {
        int d = idx >> 3, a = idx & 7;
        float acc = 0.f;
#pragma unroll 8
        for (int nn = 0; nn < NC; ++nn) acc += X[d][nn] * pw[nn][a];
        CC[d][a] = acc * sinvl[d];
    }
    __syncthreads();

    // ---- Phase 2: B_q = cov + diag(l^2/2) ----
    for (int idx = tid; idx < DD * DD; idx += 256) {
        int i = idx >> 6, j = idx & 63;
        float v = covb[idx];
        if (i == j) v += 0.5f * sl2[i];
        A[i][j] = v;
    }
    for (int idx = tid; idx < NC * DD; idx += 256) {
        int nn = idx >> 6, d = idx & 63;
        X[d][nn] = centers[idx] - smean[d];
    }
    __syncthreads();
    cholesky64_blk(A, tid);
    if (tid < DD) ldiag[tid] = 0.5f * logf(0.5f * sl2[tid]) - logf(A[tid][tid]);
    __syncthreads();
    if (tid < 32) {
        float s = ldiag[tid] + ldiag[tid + 32];
#pragma unroll
        for (int o = 16; o > 0; o >>= 1) s += __shfl_down_sync(0xffffffffu, s, o);
        if (tid == 0) s_scal[1] = expf(s);    // c_q
    }
    invert_lower64(A, U, tid);

    // ---- Y = Linv_q * D (block-triangular forward) ----
    {
        float y[8];
#pragma unroll
        for (int u = 0; u < 8; ++u) y[u] = 0.f;
#pragma unroll
        for (int kb = 0; kb < 8; ++kb) {
            float xr[8];
#pragma unroll
            for (int q = 0; q < 8; ++q) xr[q] = X[kb * 8 + q][n];
            {
                const float* ar = &A[kb * 8 + r0][kb * 8];
#pragma unroll
                for (int q = 0; q < 8; ++q)
                    if (q <= r0) y[kb] += ar[q] * xr[q];
            }
#pragma unroll
            for (int u = kb + 1; u < 8; ++u) {
                const float2* ar = (const float2*)&A[u * 8 + r0][kb * 8];
#pragma unroll
                for (int q = 0; q < 4; ++q) {
                    float2 v = ar[q];
                    y[u] += v.x * xr[2 * q];
                    y[u] += v.y * xr[2 * q + 1];
                }
            }
        }
        __syncthreads();
#pragma unroll
        for (int u = 0; u < 8; ++u) X[u * 8 + r0][n] = y[u];
    }
    __syncthreads();

    // G = Y^T Y  (32x32), 2x2 register tile, float2 loads
    {
        const int n2 = tid >> 4, m2 = tid & 15;
        const int n0 = 2 * n2, m0 = 2 * m2;
        float g00 = 0.f, g01 = 0.f, g10 = 0.f, g11 = 0.f;
        for (int d = 0; d < DD; ++d) {
            float2 a2 = *(const float2*)&X[d][n0];
            float2 b2 = *(const float2*)&X[d][m0];
            g00 += a2.x * b2.x; g01 += a2.x * b2.y;
            g10 += a2.y * b2.x; g11 += a2.y * b2.y;
        }
        G[n0][m0] = g00; G[n0][m0 + 1] = g01;
        G[n0 + 1][m0] = g10; G[n0 + 1][m0 + 1] = g11;
    }
    __syncthreads();
    if (tid < NC) gd[tid] = G[tid][tid];
    __syncthreads();
    // Q[n][m] = c_q * exp(exp1 - (G_nn + 2 G_nm + G_mm)/8)   (hot: __expf ok, args ~ -50)
    {
        float cq = s_scal[1];
        for (int p = tid; p < NC * NC; p += 256) {
            int nn = p >> 5, m = p & 31;
            G[nn][m] = cq * __expf(g_exp1[p] - 0.125f * (gd[nn] + 2.0f * G[nn][m] + gd[m]));
        }
    }
    __syncthreads();
    // P = Q W
    {
        int nn = tid >> 3, c = tid & 7;
        float acc = 0.f;
#pragma unroll 8
        for (int m = 0; m < NC; ++m) acc += G[nn][m] * W[m][c];
        pw[nn][c] = acc;
    }
    __syncthreads();
    // R = W^T P (8x8)
    if (tid < AA * AA) {
        int a = tid >> 3, c = tid & 7;
        float acc = 0.f;
        for (int nn = 0; nn < NC; ++nn) acc += W[nn][a] * pw[nn][c];
        R8[a][c] = acc;
    }
    __syncthreads();
    if (tid < AA * AA) {
        int a = tid >> 3, c = tid & 7;
        float v = 0.5f * (R8[a][c] + R8[c][a]) - s_am[a] * s_am[c];
        if (a == c) v += 1e-6f;
        ACm[a][c] = v;
    }
    __syncthreads();

    // ---- squash_sin (max_action = 1) ---- accurate libm: values can be ~1e-15,
    // sin.approx flushes tiny args to 0 (caused exact rel_err=1.0 in R7/R10).
    if (tid < AA) {
        float dc = ACm[tid][tid];
        float e = expf(-0.5f * dc);
        s_dc[tid] = dc;
        s_cd[tid] = e * cosf(s_am[tid]);           // diag of C
        out_am[(size_t)b * AA + tid] = e * sinf(s_am[tid]);
    }
    __syncthreads();
    if (tid < AA * AA) {
        int a = tid >> 3, c = tid & 7;
        float lq = -0.5f * (s_dc[a] + s_dc[c]);
        float q = expf(lq);
        float v = ACm[a][c];
        float sq = 0.5f * ((expf(lq + v) - q) * cosf(s_am[a] - s_am[c])
                         - (expf(lq - v) - q) * cosf(s_am[a] + s_am[c]));
        out_ac[(size_t)b * AA * AA + tid] = sq;
    }
    for (int idx = tid; idx < DD * AA; idx += 256) {
        int c = idx & 7;
        out_cc[(size_t)b * DD * AA + idx] = CC[idx >> 3][c] * s_cd[c];
    }
}

extern "C" void kernel_launch(void* const* d_in, const int* in_sizes, int n_in,
                              void* d_out, int out_size) {
    const float* mean = (const float*)d_in[0];
    const float* cov = (const float*)d_in[1];
    const float* centers = (const float*)d_in[2];
    const float* weights = (const float*)d_in[3];
    const float* ls = (const float*)d_in[4];
    float* out = (float*)d_out;

    int B = in_sizes[0] / DD;   // 2048
    float* out_am = out;
    float* out_ac = out + (size_t)B * AA;
    float* out_cc = out + (size_t)B * AA + (size_t)B * AA * AA;

    prep_kernel<<<1, 1024>>>(centers, ls);
    rbf_kernel<<<B, 256>>>(mean, cov, centers, weights, ls, out_am, out_ac, out_cc);
}

// round 15
// speedup vs baseline: 1.4697x; 1.4697x over previous
#include <cuda_runtime.h>
#include <math.h>

#define NB 2048
#define NC 32
#define DD 64
#define AA 8
#define XS 34   // X row stride (even -> float2-aligned rows for Gram)

// exp1[n][m] = -0.25 * sum_d (c_n[d]-c_m[d])^2 / l[d]^2   (batch-independent)
__device__ float g_exp1[NC * NC];

__global__ void prep_kernel(const float* __restrict__ centers,
                            const float* __restrict__ ls) {
    int t = threadIdx.x;           // 1024 threads = 32x32 pairs
    int n = t >> 5, m = t & 31;
    float acc = 0.f;
#pragma unroll
    for (int d = 0; d < DD; ++d) {
        float df = centers[n * DD + d] - centers[m * DD + d];
        float l = ls[d];
        acc += (df * df) / (l * l);
    }
    g_exp1[t] = -0.25f * acc;
}

// Blocked in-place Cholesky, panel width 8. Panel factor by one warp
// (rotating across warps), trailing SYRK by all 256 threads.
// A stride is ODD (65) -> all column-pattern accesses are bank-conflict-free.
__device__ __forceinline__ void cholesky64_blk(float (*A)[DD + 1], int tid) {
    const int lane = tid & 31;
    const int warp = tid >> 5;
    const int ty = tid >> 4, tx = tid & 15;
#pragma unroll 1
    for (int p = 0; p < 8; ++p) {
        const int k0 = p * 8, pe = k0 + 8;
        if (warp == (p & 7)) {
#pragma unroll 1
            for (int j = k0; j < pe; ++j) {
                float d = A[j][j];
                float inv = rsqrtf(d);
                if (lane == 0) A[j][j] = d * inv;      // sqrt(d)
                for (int i = j + 1 + lane; i < DD; i += 32) A[i][j] *= inv;
                __syncwarp();
                float cj[7];
#pragma unroll
                for (int q = 0; q < 7; ++q) {
                    int jj = j + 1 + q;
                    cj[q] = (jj < pe) ? A[jj][j] : 0.f;
                }
                for (int i = j + 1 + lane; i < DD; i += 32) {
                    float a = A[i][j];
#pragma unroll
                    for (int q = 0; q < 7; ++q) {
                        int jj = j + 1 + q;
                        if (jj < pe) A[i][jj] -= a * cj[q];
                    }
                }
                __syncwarp();
            }
        }
        __syncthreads();
        if (pe < DD) {
            for (int i = pe + ty; i < DD; i += 16) {
                float ai[8];
#pragma unroll
                for (int kk = 0; kk < 8; ++kk) ai[kk] = A[i][k0 + kk];
                for (int j = pe + tx; j <= i; j += 16) {
                    float acc = A[i][j];
#pragma unroll
                    for (int kk = 0; kk < 8; ++kk) acc -= ai[kk] * A[j][k0 + kk];
                    A[i][j] = acc;
                }
            }
            __syncthreads();
        }
    }
}

// In-place inversion of lower-triangular L (64x64) held in A (lower+diag).
// U scratch: >= 3*16*17 floats. Result: A holds Linv (lower+diag), and the
// upper triangle of each 16x16 diagonal block is ZEROED.
__device__ __forceinline__ void invert_lower64(float (*A)[DD + 1],
                                               float* U, int tid) {
    const int lane = tid & 31;
    const int warp = tid >> 5;
    if (warp < 4) {
        const int b0 = warp * 16;
        const int j = lane;
#pragma unroll 1
        for (int i = 0; i < 16; ++i) {
            float s = 0.f;
            if (j < i) {
                for (int k = j; k < i; ++k) s += A[b0 + i][b0 + k] * A[b0 + k][b0 + j];
            }
            float di = A[b0 + i][b0 + i];
            __syncwarp();
            if (j < i)            A[b0 + i][b0 + j] = -s / di;
            else if (j == i)      A[b0 + i][b0 + i] = 1.0f / di;
            else if (j < 16)      A[b0 + i][b0 + j] = 0.0f;   // zero upper
            __syncwarp();
        }
    }
    __syncthreads();
    const int r = tid >> 4, c = tid & 15;
#pragma unroll 1
    for (int bj = 2; bj >= 0; --bj) {
        const int nb = 3 - bj;
        for (int m = 0; m < nb; ++m) {
            const int bi = bj + 1 + m;
            float acc = 0.f;
            for (int bk = bj + 1; bk <= bi; ++bk) {
#pragma unroll
                for (int kk = 0; kk < 16; ++kk)
                    acc += A[bi * 16 + r][bk * 16 + kk] * A[bk * 16 + kk][bj * 16 + c];
            }
            U[m * 272 + r * 17 + c] = acc;
        }
        __syncthreads();
        for (int m = 0; m < nb; ++m) {
            const int bi = bj + 1 + m;
            float acc = 0.f;
#pragma unroll
            for (int kk = 0; kk < 16; ++kk)
                acc += U[m * 272 + r * 17 + kk] * A[bj * 16 + kk][bj * 16 + c];
            A[bi * 16 + r][bj * 16 + c] = -acc;
        }
        __syncthreads();
    }
}

__global__ __launch_bounds__(256, 4) void rbf_kernel(
    const float* __restrict__ mean, const float* __restrict__ cov,
    const float* __restrict__ centers, const float* __restrict__ weights,
    const float* __restrict__ ls,
    float* __restrict__ out_am, float* __restrict__ out_ac,
    float* __restrict__ out_cc) {
    __shared__ float A[DD][DD + 1];     // matrix -> L -> Linv (both phases)
    __shared__ __align__(8) float X[DD][XS];  // RHS / solutions (D-major)
    __shared__ float CC[DD][AA];        // cross_cov pre-squash
    __shared__ float G[NC][NC + 1];     // scratch (inversion U) -> Gram -> Q
    __shared__ float W[NC][AA];
    __shared__ float pw[NC][AA];        // phi*W, later P = Q W
    __shared__ float phi[NC];
    __shared__ float cp[8][NC];         // column-norm partials
    __shared__ float smean[DD], sinvl[DD], sl2[DD];
    __shared__ float ldiag[DD];
    __shared__ float s_scal[2];         // [0]=normalizer, [1]=c_q
    __shared__ float s_am[AA], s_dc[AA], s_cd[AA];
    __shared__ float R8[AA][AA + 1];
    __shared__ float ACm[AA][AA + 1];
    __shared__ float gd[NC];

    const int tid = threadIdx.x;
    const int b = blockIdx.x;
    const float* covb = cov + (size_t)b * DD * DD;
    const float* meanb = mean + (size_t)b * DD;
    float* U = &G[0][0];
    const int n = tid & 31, r0 = tid >> 5;   // apply-phase mapping

    if (tid < DD) {
        float l = ls[tid];
        smean[tid] = meanb[tid];
        sinvl[tid] = 1.0f / l;
        sl2[tid] = l * l;
    }
    {
        int nn = tid >> 3, a = tid & 7;
        W[nn][a] = weights[tid];
    }
    __syncthreads();

    // A = diag(invl) cov diag(invl) + I ; X[d][n] = (c_n[d]-mean[d])*invl[d]
    for (int idx = tid; idx < DD * DD; idx += 256) {
        int i = idx >> 6, j = idx & 63;
        float v = covb[idx] * sinvl[i] * sinvl[j];
        if (i == j) v += 1.0f;
        A[i][j] = v;
    }
    for (int idx = tid; idx < NC * DD; idx += 256) {
        int nn = idx >> 6, d = idx & 63;
        X[d][nn] = (centers[idx] - smean[d]) * sinvl[d];
    }
    __syncthreads();

    cholesky64_blk(A, tid);
    if (tid < DD) ldiag[tid] = logf(A[tid][tid]);
    __syncthreads();
    if (tid < 32) {   // warp-parallel logdet reduce (replaces tid0 serial loop)
        float s = ldiag[tid] + ldiag[tid + 32];
#pragma unroll
        for (int o = 16; o > 0; o >>= 1) s += __shfl_down_sync(0xffffffffu, s, o);
        if (tid == 0) s_scal[0] = expf(-s);   // exp(-0.5*logdet)
    }
    invert_lower64(A, U, tid);

    // Y1 = Linv * S  (k-outer, A[i][k] warp-broadcast), colnorms -> cp
    {
        float y[8];
#pragma unroll
        for (int u = 0; u < 8; ++u) y[u] = 0.f;
        for (int k = 0; k < DD; ++k) {
            float xk = X[k][n];
#pragma unroll
            for (int u = 0; u < 8; ++u) {
                int i = u * 8 + r0;
                if (i >= k) y[u] += A[i][k] * xk;
            }
        }
        float pn = 0.f;
#pragma unroll
        for (int u = 0; u < 8; ++u) pn += y[u] * y[u];
        cp[r0][n] = pn;
        __syncthreads();                   // all reads of X done
#pragma unroll
        for (int u = 0; u < 8; ++u) X[u * 8 + r0][n] = y[u];
        __syncthreads();
        // T = Linv^T * Y1
#pragma unroll
        for (int u = 0; u < 8; ++u) y[u] = 0.f;
        for (int k = 0; k < DD; ++k) {
            float xk = X[k][n];
#pragma unroll
            for (int u = 0; u < 8; ++u) {
                int i = u * 8 + r0;
                if (k >= i) y[u] += A[k][i] * xk;
            }
        }
        __syncthreads();
#pragma unroll
        for (int u = 0; u < 8; ++u) X[u * 8 + r0][n] = y[u];
    }
    __syncthreads();

    // phi[n] = normalizer * exp(-0.5 * |Y1 col n|^2)   (accurate expf: tiny values)
    if (tid < NC) {
        float acc = 0.f;
#pragma unroll
        for (int u = 0; u < 8; ++u) acc += cp[u][tid];
        phi[tid] = expf(-0.5f * acc) * s_scal[0];
    }
    __syncthreads();
    {
        int nn = tid >> 3, a = tid & 7;
        pw[nn][a] = phi[nn] * W[nn][a];
    }
    __syncthreads();
    if (tid < AA) {
        float s = 0.f;
        for (int nn = 0; nn < NC; ++nn) s += pw[nn][tid];
        s_am[tid] = s;
    }
    // cross_cov[d][a] = invl[d] * sum_n t^T[d][n] * (phi W)[n][a]
    for (int idx = tid; idx < DD * AA; idx += 256) {
        int d = idx >> 3, a = idx & 7;
        float acc = 0.f;
#pragma unroll 8
        for (int nn = 0; nn < NC; ++nn) acc += X[d][nn] * pw[nn][a];
        CC[d][a] = acc * sinvl[d];
    }
    __syncthreads();

    // ---- Phase 2: B_q = cov + diag(l^2/2) ----
    for (int idx = tid; idx < DD * DD; idx += 256) {
        int i = idx >> 6, j = idx & 63;
        float v = covb[idx];
        if (i == j) v += 0.5f * sl2[i];
        A[i][j] = v;
    }
    for (int idx = tid; idx < NC * DD; idx += 256) {
        int nn = idx >> 6, d = idx & 63;
        X[d][nn] = centers[idx] - smean[d];
    }
    __syncthreads();
    cholesky64_blk(A, tid);
    if (tid < DD) ldiag[tid] = 0.5f * logf(0.5f * sl2[tid]) - logf(A[tid][tid]);
    __syncthreads();
    if (tid < 32) {
        float s = ldiag[tid] + ldiag[tid + 32];
#pragma unroll
        for (int o = 16; o > 0; o >>= 1) s += __shfl_down_sync(0xffffffffu, s, o);
        if (tid == 0) s_scal[1] = expf(s);    // c_q
    }
    invert_lower64(A, U, tid);

    // Y = Linv_q * D (k-outer)
    {
        float y[8];
#pragma unroll
        for (int u = 0; u < 8; ++u) y[u] = 0.f;
        for (int k = 0; k < DD; ++k) {
            float xk = X[k][n];
#pragma unroll
            for (int u = 0; u < 8; ++u) {
                int i = u * 8 + r0;
                if (i >= k) y[u] += A[i][k] * xk;
            }
        }
        __syncthreads();
#pragma unroll
        for (int u = 0; u < 8; ++u) X[u * 8 + r0][n] = y[u];
    }
    __syncthreads();

    // G = Y^T Y  (32x32), 2x2 register tile, float2 X loads (rows 8B-aligned)
    {
        const int n2 = tid >> 4, m2 = tid & 15;
        const int n0 = 2 * n2, m0 = 2 * m2;
        float g00 = 0.f, g01 = 0.f, g10 = 0.f, g11 = 0.f;
        for (int d = 0; d < DD; ++d) {
            float2 a2 = *(const float2*)&X[d][n0];
            float2 b2 = *(const float2*)&X[d][m0];
            g00 += a2.x * b2.x; g01 += a2.x * b2.y;
            g10 += a2.y * b2.x; g11 += a2.y * b2.y;
        }
        G[n0][m0] = g00; G[n0][m0 + 1] = g01;
        G[n0 + 1][m0] = g10; G[n0 + 1][m0 + 1] = g11;
    }
    __syncthreads();
    if (tid < NC) gd[tid] = G[tid][tid];
    __syncthreads();
    // Q[n][m] = c_q * exp(exp1 - (G_nn + 2 G_nm + G_mm)/8)   (hot: __expf ok, args ~ -50)
    {
        float cq = s_scal[1];
        for (int p = tid; p < NC * NC; p += 256) {
            int nn = p >> 5, m = p & 31;
            G[nn][m] = cq * __expf(g_exp1[p] - 0.125f * (gd[nn] + 2.0f * G[nn][m] + gd[m]));
        }
    }
    __syncthreads();
    // P = Q W
    {
        int nn = tid >> 3, c = tid & 7;
        float acc = 0.f;
#pragma unroll 8
        for (int m = 0; m < NC; ++m) acc += G[nn][m] * W[m][c];
        pw[nn][c] = acc;
    }
    __syncthreads();
    // R = W^T P (8x8)
    if (tid < AA * AA) {
        int a = tid >> 3, c = tid & 7;
        float acc = 0.f;
        for (int nn = 0; nn < NC; ++nn) acc += W[nn][a] * pw[nn][c];
        R8[a][c] = acc;
    }
    __syncthreads();
    if (tid < AA * AA) {
        int a = tid >> 3, c = tid & 7;
        float v = 0.5f * (R8[a][c] + R8[c][a]) - s_am[a] * s_am[c];
        if (a == c) v += 1e-6f;
        ACm[a][c] = v;
    }
    __syncthreads();

    // ---- squash_sin (max_action = 1) ---- accurate libm: values can be ~1e-15,
    // sin.approx flushes tiny args to 0 (caused exact rel_err=1.0 in R7/R10).
    if (tid < AA) {
        float dc = ACm[tid][tid];
        float e = expf(-0.5f * dc);
        s_dc[tid] = dc;
        s_cd[tid] = e * cosf(s_am[tid]);           // diag of C
        out_am[(size_t)b * AA + tid] = e * sinf(s_am[tid]);
    }
    __syncthreads();
    if (tid < AA * AA) {
        int a = tid >> 3, c = tid & 7;
        float lq = -0.5f * (s_dc[a] + s_dc[c]);
        float q = expf(lq);
        float v = ACm[a][c];
        float sq = 0.5f * ((expf(lq + v) - q) * cosf(s_am[a] - s_am[c])
                         - (expf(lq - v) - q) * cosf(s_am[a] + s_am[c]));
        out_ac[(size_t)b * AA * AA + tid] = sq;
    }
    for (int idx = tid; idx < DD * AA; idx += 256) {
        int c = idx & 7;
        out_cc[(size_t)b * DD * AA + idx] = CC[idx >> 3][c] * s_cd[c];
    }
}

extern "C" void kernel_launch(void* const* d_in, const int* in_sizes, int n_in,
                              void* d_out, int out_size) {
    const float* mean = (const float*)d_in[0];
    const float* cov = (const float*)d_in[1];
    const float* centers = (const float*)d_in[2];
    const float* weights = (const float*)d_in[3];
    const float* ls = (const float*)d_in[4];
    float* out = (float*)d_out;

    int B = in_sizes[0] / DD;   // 2048
    float* out_am = out;
    float* out_ac = out + (size_t)B * AA;
    float* out_cc = out + (size_t)B * AA + (size_t)B * AA * AA;

    prep_kernel<<<1, 1024>>>(centers, ls);
    rbf_kernel<<<B, 256>>>(mean, cov, centers, weights, ls, out_am, out_ac, out_cc);
}

// round 16
// speedup vs baseline: 1.5621x; 1.0629x over previous
#include <cuda_runtime.h>
#include <math.h>

#define NB 2048
#define NC 32
#define DD 64
#define AA 8
#define XS 34   // X row stride (even -> float2-aligned rows for Gram)

// exp1[n][m] = -0.25 * sum_d (c_n[d]-c_m[d])^2 / l[d]^2   (batch-independent)
__device__ float g_exp1[NC * NC];

__global__ void prep_kernel(const float* __restrict__ centers,
                            const float* __restrict__ ls) {
    int t = threadIdx.x;           // 1024 threads = 32x32 pairs
    int n = t >> 5, m = t & 31;
    float acc = 0.f;
#pragma unroll
    for (int d = 0; d < DD; ++d) {
        float df = centers[n * DD + d] - centers[m * DD + d];
        float l = ls[d];
        acc += (df * df) / (l * l);
    }
    g_exp1[t] = -0.25f * acc;
}

// Blocked in-place Cholesky, panel width 8. Panel factor by one warp
// (rotating across warps), trailing SYRK by all 256 threads.
// A stride is ODD (65) -> all column-pattern accesses are bank-conflict-free.
__device__ __forceinline__ void cholesky64_blk(float (*A)[DD + 1], int tid) {
    const int lane = tid & 31;
    const int warp = tid >> 5;
    const int ty = tid >> 4, tx = tid & 15;
#pragma unroll 1
    for (int p = 0; p < 8; ++p) {
        const int k0 = p * 8, pe = k0 + 8;
        if (warp == (p & 7)) {
#pragma unroll 1
            for (int j = k0; j < pe; ++j) {
                float d = A[j][j];
                float inv = rsqrtf(d);
                if (lane == 0) A[j][j] = d * inv;      // sqrt(d)
                for (int i = j + 1 + lane; i < DD; i += 32) A[i][j] *= inv;
                __syncwarp();
                float cj[7];
#pragma unroll
                for (int q = 0; q < 7; ++q) {
                    int jj = j + 1 + q;
                    cj[q] = (jj < pe) ? A[jj][j] : 0.f;
                }
                for (int i = j + 1 + lane; i < DD; i += 32) {
                    float a = A[i][j];
#pragma unroll
                    for (int q = 0; q < 7; ++q) {
                        int jj = j + 1 + q;
                        if (jj < pe) A[i][jj] -= a * cj[q];
                    }
                }
                __syncwarp();
            }
        }
        __syncthreads();
        if (pe < DD) {
            for (int i = pe + ty; i < DD; i += 16) {
                float ai[8];
#pragma unroll
                for (int kk = 0; kk < 8; ++kk) ai[kk] = A[i][k0 + kk];
                for (int j = pe + tx; j <= i; j += 16) {
                    float acc = A[i][j];
#pragma unroll
                    for (int kk = 0; kk < 8; ++kk) acc -= ai[kk] * A[j][k0 + kk];
                    A[i][j] = acc;
                }
            }
            __syncthreads();
        }
    }
}

// In-place inversion of lower-triangular L (64x64) held in A (lower+diag).
// U scratch: >= 3*16*17 floats. Result: A holds Linv (lower+diag), and the
// upper triangle of each 16x16 diagonal block is ZEROED.
__device__ __forceinline__ void invert_lower64(float (*A)[DD + 1],
                                               float* U, int tid) {
    const int lane = tid & 31;
    const int warp = tid >> 5;
    if (warp < 4) {
        const int b0 = warp * 16;
        const int j = lane;
#pragma unroll 1
        for (int i = 0; i < 16; ++i) {
            float s = 0.f;
            if (j < i) {
                for (int k = j; k < i; ++k) s += A[b0 + i][b0 + k] * A[b0 + k][b0 + j];
            }
            float di = A[b0 + i][b0 + i];
            __syncwarp();
            if (j < i)            A[b0 + i][b0 + j] = -s / di;
            else if (j == i)      A[b0 + i][b0 + i] = 1.0f / di;
            else if (j < 16)      A[b0 + i][b0 + j] = 0.0f;   // zero upper
            __syncwarp();
        }
    }
    __syncthreads();
    const int r = tid >> 4, c = tid & 15;
#pragma unroll 1
    for (int bj = 2; bj >= 0; --bj) {
        const int nb = 3 - bj;
        for (int m = 0; m < nb; ++m) {
            const int bi = bj + 1 + m;
            float acc = 0.f;
            for (int bk = bj + 1; bk <= bi; ++bk) {
#pragma unroll
                for (int kk = 0; kk < 16; ++kk)
                    acc += A[bi * 16 + r][bk * 16 + kk] * A[bk * 16 + kk][bj * 16 + c];
            }
            U[m * 272 + r * 17 + c] = acc;
        }
        __syncthreads();
        for (int m = 0; m < nb; ++m) {
            const int bi = bj + 1 + m;
            float acc = 0.f;
#pragma unroll
            for (int kk = 0; kk < 16; ++kk)
                acc += U[m * 272 + r * 17 + kk] * A[bj * 16 + kk][bj * 16 + c];
            A[bi * 16 + r][bj * 16 + c] = -acc;
        }
        __syncthreads();
    }
}

__global__ __launch_bounds__(256, 4) void rbf_kernel(
    const float* __restrict__ mean, const float* __restrict__ cov,
    const float* __restrict__ centers, const float* __restrict__ weights,
    const float* __restrict__ ls,
    float* __restrict__ out_am, float* __restrict__ out_ac,
    float* __restrict__ out_cc) {
    __shared__ float A[DD][DD + 1];     // matrix -> L -> Linv (both phases)
    __shared__ __align__(8) float X[DD][XS];  // RHS / solutions (D-major)
    __shared__ float CC[DD][AA];        // cross_cov pre-squash
    __shared__ float G[NC][NC + 1];     // scratch (inversion U) -> Gram -> Q
    __shared__ float W[NC][AA];
    __shared__ float pw[NC][AA];        // phi*W, later P = Q W
    __shared__ float phi[NC];
    __shared__ float cp[8][NC];         // column-norm partials
    __shared__ float smean[DD], sinvl[DD], sl2[DD];
    __shared__ float ldiag[DD];
    __shared__ float s_scal[2];         // [0]=normalizer, [1]=c_q
    __shared__ float s_am[AA], s_dc[AA], s_cd[AA];
    __shared__ float R8[AA][AA + 1];
    __shared__ float ACm[AA][AA + 1];
    __shared__ float gd[NC];

    const int tid = threadIdx.x;
    const int b = blockIdx.x;
    const float* covb = cov + (size_t)b * DD * DD;
    const float* meanb = mean + (size_t)b * DD;
    float* U = &G[0][0];
    const int n = tid & 31, r0 = tid >> 5;   // apply mapping; r0 is warp-uniform

    if (tid < DD) {
        float l = ls[tid];
        smean[tid] = meanb[tid];
        sinvl[tid] = 1.0f / l;
        sl2[tid] = l * l;
    }
    {
        int nn = tid >> 3, a = tid & 7;
        W[nn][a] = weights[tid];
    }
    __syncthreads();

    // A = diag(invl) cov diag(invl) + I ; X[d][n] = (c_n[d]-mean[d])*invl[d]
    for (int idx = tid; idx < DD * DD; idx += 256) {
        int i = idx >> 6, j = idx & 63;
        float v = covb[idx] * sinvl[i] * sinvl[j];
        if (i == j) v += 1.0f;
        A[i][j] = v;
    }
    for (int idx = tid; idx < NC * DD; idx += 256) {
        int nn = idx >> 6, d = idx & 63;
        X[d][nn] = (centers[idx] - smean[d]) * sinvl[d];
    }
    __syncthreads();

    cholesky64_blk(A, tid);
    if (tid < DD) ldiag[tid] = logf(A[tid][tid]);
    __syncthreads();
    if (tid < 32) {   // warp-parallel logdet reduce
        float s = ldiag[tid] + ldiag[tid + 32];
#pragma unroll
        for (int o = 16; o > 0; o >>= 1) s += __shfl_down_sync(0xffffffffu, s, o);
        if (tid == 0) s_scal[0] = expf(-s);   // exp(-0.5*logdet)
    }
    invert_lower64(A, U, tid);

    // ---- Y1 = Linv * S (compile-time block-triangular; no dead slots) ----
    {
        float y[8];
#pragma unroll
        for (int u = 0; u < 8; ++u) y[u] = 0.f;
#pragma unroll
        for (int kb = 0; kb < 8; ++kb) {
#pragma unroll
            for (int q = 0; q < 8; ++q) {           // dense blocks u > kb
                const int k = kb * 8 + q;
                const float xk = X[k][n];
#pragma unroll
                for (int u = kb + 1; u < 8; ++u)
                    y[u] += A[u * 8 + r0][k] * xk;  // broadcast LDS
            }
            {   // diagonal block u == kb: k = kb*8+q, q <= r0 (uniform trip)
                const float* ar = &A[kb * 8 + r0][kb * 8];
                for (int q = 0; q <= r0; ++q)
                    y[kb] += ar[q] * X[kb * 8 + q][n];
            }
        }
        float pn = 0.f;
#pragma unroll
        for (int u = 0; u < 8; ++u) pn += y[u] * y[u];
        cp[r0][n] = pn;
        __syncthreads();                   // all reads of X done
#pragma unroll
        for (int u = 0; u < 8; ++u) X[u * 8 + r0][n] = y[u];
        __syncthreads();

        // ---- T = Linv^T * Y1 (block-triangular transpose) ----
#pragma unroll
        for (int u = 0; u < 8; ++u) y[u] = 0.f;
#pragma unroll
        for (int kb = 0; kb < 8; ++kb) {
#pragma unroll
            for (int q = 0; q < 8; ++q) {           // dense blocks u < kb
                const int k = kb * 8 + q;
                const float xk = X[k][n];
#pragma unroll
                for (int u = 0; u < kb; ++u)
                    y[u] += A[k][u * 8 + r0] * xk;  // broadcast LDS
            }
            // diagonal block u == kb: q >= r0 (uniform trip)
            for (int q = r0; q < 8; ++q)
                y[kb] += A[kb * 8 + q][kb * 8 + r0] * X[kb * 8 + q][n];
        }
        __syncthreads();
#pragma unroll
        for (int u = 0; u < 8; ++u) X[u * 8 + r0][n] = y[u];
    }
    __syncthreads();

    // phi[n] = normalizer * exp(-0.5 * |Y1 col n|^2)   (accurate expf: tiny values)
    if (tid < NC) {
        float acc = 0.f;
#pragma unroll
        for (int u = 0; u < 8; ++u) acc += cp[u][tid];
        phi[tid] = expf(-0.5f * acc) * s_scal[0];
    }
    __syncthreads();
    {
        int nn = tid >> 3, a = tid & 7;
        pw[nn][a] = phi[nn] * W[nn][a];
    }
    __syncthreads();
    if (tid < AA) {
        float s = 0.f;
        for (int nn = 0; nn < NC; ++nn) s += pw[nn][tid];
        s_am[tid] = s;
    }
    // cross_cov[d][a] = invl[d] * sum_n t^T[d][n] * (phi W)[n][a]
    for (int idx = tid; idx < DD * AA; idx += 256) {
        int d = idx >> 3, a = idx & 7;
        float acc = 0.f;
#pragma unroll 8
        for (int nn = 0; nn < NC; ++nn) acc += X[d][nn] * pw[nn][a];
        CC[d][a] = acc * sinvl[d];
    }
    __syncthreads();

    // ---- Phase 2: B_q = cov + diag(l^2/2) ----
    for (int idx = tid; idx < DD * DD; idx += 256) {
        int i = idx >> 6, j = idx & 63;
        float v = covb[idx];
        if (i == j) v += 0.5f * sl2[i];
        A[i][j] = v;
    }
    for (int idx = tid; idx < NC * DD; idx += 256) {
        int nn = idx >> 6, d = idx & 63;
        X[d][nn] = centers[idx] - smean[d];
    }
    __syncthreads();
    cholesky64_blk(A, tid);
    if (tid < DD) ldiag[tid] = 0.5f * logf(0.5f * sl2[tid]) - logf(A[tid][tid]);
    __syncthreads();
    if (tid < 32) {
        float s = ldiag[tid] + ldiag[tid + 32];
#pragma unroll
        for (int o = 16; o > 0; o >>= 1) s += __shfl_down_sync(0xffffffffu, s, o);
        if (tid == 0) s_scal[1] = expf(s);    // c_q
    }
    invert_lower64(A, U, tid);

    // ---- Y = Linv_q * D (block-triangular forward) ----
    {
        float y[8];
#pragma unroll
        for (int u = 0; u < 8; ++u) y[u] = 0.f;
#pragma unroll
        for (int kb = 0; kb < 8; ++kb) {
#pragma unroll
            for (int q = 0; q < 8; ++q) {
                const int k = kb * 8 + q;
                const float xk = X[k][n];
#pragma unroll
                for (int u = kb + 1; u < 8; ++u)
                    y[u] += A[u * 8 + r0][k] * xk;
            }
            {
                const float* ar = &A[kb * 8 + r0][kb * 8];
                for (int q = 0; q <= r0; ++q)
                    y[kb] += ar[q] * X[kb * 8 + q][n];
            }
        }
        __syncthreads();
#pragma unroll
        for (int u = 0; u < 8; ++u) X[u * 8 + r0][n] = y[u];
    }
    __syncthreads();

    // G = Y^T Y  (32x32), 2x2 register tile, float2 X loads (rows 8B-aligned)
    {
        const int n2 = tid >> 4, m2 = tid & 15;
        const int n0 = 2 * n2, m0 = 2 * m2;
        float g00 = 0.f, g01 = 0.f, g10 = 0.f, g11 = 0.f;
        for (int d = 0; d < DD; ++d) {
            float2 a2 = *(const float2*)&X[d][n0];
            float2 b2 = *(const float2*)&X[d][m0];
            g00 += a2.x * b2.x; g01 += a2.x * b2.y;
            g10 += a2.y * b2.x; g11 += a2.y * b2.y;
        }
        G[n0][m0] = g00; G[n0][m0 + 1] = g01;
        G[n0 + 1][m0] = g10; G[n0 + 1][m0 + 1] = g11;
    }
    __syncthreads();
    if (tid < NC) gd[tid] = G[tid][tid];
    __syncthreads();
    // Q[n][m] = c_q * exp(exp1 - (G_nn + 2 G_nm + G_mm)/8)   (hot: __expf ok, args ~ -50)
    {
        float cq = s_scal[1];
        for (int p = tid; p < NC * NC; p += 256) {
            int nn = p >> 5, m = p & 31;
            G[nn][m] = cq * __expf(g_exp1[p] - 0.125f * (gd[nn] + 2.0f * G[nn][m] + gd[m]));
        }
    }
    __syncthreads();
    // P = Q W
    {
        int nn = tid >> 3, c = tid & 7;
        float acc = 0.f;
#pragma unroll 8
        for (int m = 0; m < NC; ++m) acc += G[nn][m] * W[m][c];
        pw[nn][c] = acc;
    }
    __syncthreads();
    // R = W^T P (8x8)
    if (tid < AA * AA) {
        int a = tid >> 3, c = tid & 7;
        float acc = 0.f;
        for (int nn = 0; nn < NC; ++nn) acc += W[nn][a] * pw[nn][c];
        R8[a][c] = acc;
    }
    __syncthreads();
    if (tid < AA * AA) {
        int a = tid >> 3, c = tid & 7;
        float v = 0.5f * (R8[a][c] + R8[c][a]) - s_am[a] * s_am[c];
        if (a == c) v += 1e-6f;
        ACm[a][c] = v;
    }
    __syncthreads();

    // ---- squash_sin (max_action = 1) ---- accurate libm: values can be ~1e-15,
    // sin.approx flushes tiny args to 0 (caused exact rel_err=1.0 in R7/R10).
    if (tid < AA) {
        float dc = ACm[tid][tid];
        float e = expf(-0.5f * dc);
        s_dc[tid] = dc;
        s_cd[tid] = e * cosf(s_am[tid]);           // diag of C
        out_am[(size_t)b * AA + tid] = e * sinf(s_am[tid]);
    }
    __syncthreads();
    if (tid < AA * AA) {
        int a = tid >> 3, c = tid & 7;
        float lq = -0.5f * (s_dc[a] + s_dc[c]);
        float q = expf(lq);
        float v = ACm[a][c];
        float sq = 0.5f * ((expf(lq + v) - q) * cosf(s_am[a] - s_am[c])
                         - (expf(lq - v) - q) * cosf(s_am[a] + s_am[c]));
        out_ac[(size_t)b * AA * AA + tid] = sq;
    }
    for (int idx = tid; idx < DD * AA; idx += 256) {
        int c = idx & 7;
        out_cc[(size_t)b * DD * AA + idx] = CC[idx >> 3][c] * s_cd[c];
    }
}

extern "C" void kernel_launch(void* const* d_in, const int* in_sizes, int n_in,
                              void* d_out, int out_size) {
    const float* mean = (const float*)d_in[0];
    const float* cov = (const float*)d_in[1];
    const float* centers = (const float*)d_in[2];
    const float* weights = (const float*)d_in[3];
    const float* ls = (const float*)d_in[4];
    float* out = (float*)d_out;

    int B = in_sizes[0] / DD;   // 2048
    float* out_am = out;
    float* out_ac = out + (size_t)B * AA;
    float* out_cc = out + (size_t)B * AA + (size_t)B * AA * AA;

    prep_kernel<<<1, 1024>>>(centers, ls);
    rbf_kernel<<<B, 256>>>(mean, cov, centers, weights, ls, out_am, out_ac, out_cc);
}

// round 17
// speedup vs baseline: 1.8442x; 1.1806x over previous
#include <cuda_runtime.h>
#include <math.h>

#define NB 2048
#define NC 32
#define DD 64
#define AA 8
#define XS 34   // X row stride (even -> float2-aligned rows)
#define TT 128  // threads per CTA (phase kernels)

// exp1[n][m] = -0.25 * sum_d (c_n[d]-c_m[d])^2 / l[d]^2   (batch-independent)
__device__ float g_exp1[NC * NC];
// phase2 -> phase1 handoff: R[b][a][c] = (W^T Q W)[a][c]
__device__ float gRbuf[NB * AA * AA];

__global__ void prep_kernel(const float* __restrict__ centers,
                            const float* __restrict__ ls) {
    int t = threadIdx.x;           // 1024 threads = 32x32 pairs
    int n = t >> 5, m = t & 31;
    float acc = 0.f;
#pragma unroll
    for (int d = 0; d < DD; ++d) {
        float df = centers[n * DD + d] - centers[m * DD + d];
        float l = ls[d];
        acc += (df * df) / (l * l);
    }
    g_exp1[t] = -0.25f * acc;
}

// Blocked in-place Cholesky, panel width 8, 128 threads.
// Panel by one warp (rotating over 4), trailing SYRK by all 128.
__device__ __forceinline__ void cholesky64_128(float (*A)[DD + 1], int tid) {
    const int lane = tid & 31;
    const int warp = tid >> 5;            // 0..3
    const int ty = tid >> 4, tx = tid & 15;   // ty 0..7
#pragma unroll 1
    for (int p = 0; p < 8; ++p) {
        const int k0 = p * 8, pe = k0 + 8;
        if (warp == (p & 3)) {
#pragma unroll 1
            for (int j = k0; j < pe; ++j) {
                float d = A[j][j];
                float inv = rsqrtf(d);
                if (lane == 0) A[j][j] = d * inv;      // sqrt(d)
                for (int i = j + 1 + lane; i < DD; i += 32) A[i][j] *= inv;
                __syncwarp();
                float cj[7];
#pragma unroll
                for (int q = 0; q < 7; ++q) {
                    int jj = j + 1 + q;
                    cj[q] = (jj < pe) ? A[jj][j] : 0.f;
                }
                for (int i = j + 1 + lane; i < DD; i += 32) {
                    float a = A[i][j];
#pragma unroll
                    for (int q = 0; q < 7; ++q) {
                        int jj = j + 1 + q;
                        if (jj < pe) A[i][jj] -= a * cj[q];
                    }
                }
                __syncwarp();
            }
        }
        __syncthreads();
        if (pe < DD) {
            for (int i = pe + ty; i < DD; i += 8) {
                float ai[8];
#pragma unroll
                for (int kk = 0; kk < 8; ++kk) ai[kk] = A[i][k0 + kk];
                for (int j = pe + tx; j <= i; j += 16) {
                    float acc = A[i][j];
#pragma unroll
                    for (int kk = 0; kk < 8; ++kk) acc -= ai[kk] * A[j][k0 + kk];
                    A[i][j] = acc;
                }
            }
            __syncthreads();
        }
    }
}

// In-place inversion of lower-triangular L (64x64), 128 threads.
// U scratch >= 816 floats. Result: Linv in lower+diag; upper triangle of
// each 16x16 diagonal block ZEROED.
__device__ __forceinline__ void invert_lower64_128(float (*A)[DD + 1],
                                                   float* U, int tid) {
    const int lane = tid & 31;
    const int warp = tid >> 5;   // 0..3, one 16x16 diag block each
    {
        const int b0 = warp * 16;
        const int j = lane;
#pragma unroll 1
        for (int i = 0; i < 16; ++i) {
            float s = 0.f;
            if (j < i) {
                for (int k = j; k < i; ++k) s += A[b0 + i][b0 + k] * A[b0 + k][b0 + j];
            }
            float di = A[b0 + i][b0 + i];
            __syncwarp();
            if (j < i)            A[b0 + i][b0 + j] = -s / di;
            else if (j == i)      A[b0 + i][b0 + i] = 1.0f / di;
            else if (j < 16)      A[b0 + i][b0 + j] = 0.0f;   // zero upper
            __syncwarp();
        }
    }
    __syncthreads();
    const int r8 = tid >> 4;     // 0..7
    const int c = tid & 15;
#pragma unroll 1
    for (int bj = 2; bj >= 0; --bj) {
        const int nb = 3 - bj;
        for (int m = 0; m < nb; ++m) {
            const int bi = bj + 1 + m;
#pragma unroll 1
            for (int rh = 0; rh < 2; ++rh) {
                const int r = r8 + 8 * rh;
                float acc = 0.f;
                for (int bk = bj + 1; bk <= bi; ++bk) {
#pragma unroll
                    for (int kk = 0; kk < 16; ++kk)
                        acc += A[bi * 16 + r][bk * 16 + kk] * A[bk * 16 + kk][bj * 16 + c];
                }
                U[m * 272 + r * 17 + c] = acc;
            }
        }
        __syncthreads();
        for (int m = 0; m < nb; ++m) {
            const int bi = bj + 1 + m;
#pragma unroll 1
            for (int rh = 0; rh < 2; ++rh) {
                const int r = r8 + 8 * rh;
                float acc = 0.f;
#pragma unroll
                for (int kk = 0; kk < 16; ++kk)
                    acc += U[m * 272 + r * 17 + kk] * A[bj * 16 + kk][bj * 16 + c];
                A[bi * 16 + r][bj * 16 + c] = -acc;
            }
        }
        __syncthreads();
    }
}

// Y = Linv * X in place (block-triangular, 2 column passes of 16 cols).
// If cpb != 0, also writes per-thread column-norm partials cpb[r0*32+n].
__device__ __forceinline__ void apply_fwd_128(const float (*A)[DD + 1],
                                              float (*X)[XS], float* cpb, int tid) {
    const int nb = tid & 15, r0 = tid >> 4;
#pragma unroll 1
    for (int pass = 0; pass < 2; ++pass) {
        const int n = nb + 16 * pass;
        float y[8];
#pragma unroll
        for (int u = 0; u < 8; ++u) y[u] = 0.f;
#pragma unroll
        for (int kb = 0; kb < 8; ++kb) {
#pragma unroll
            for (int q = 0; q < 8; ++q) {           // dense blocks u > kb
                const int k = kb * 8 + q;
                const float xk = X[k][n];
#pragma unroll
                for (int u = kb + 1; u < 8; ++u)
                    y[u] += A[u * 8 + r0][k] * xk;
            }
            const float* ar = &A[kb * 8 + r0][kb * 8];  // diag block, q <= r0
            for (int q = 0; q <= r0; ++q)
                y[kb] += ar[q] * X[kb * 8 + q][n];
        }
        if (cpb) {
            float pn = 0.f;
#pragma unroll
            for (int u = 0; u < 8; ++u) pn += y[u] * y[u];
            cpb[r0 * 32 + n] = pn;
        }
        __syncthreads();                 // all reads of this column set done
#pragma unroll
        for (int u = 0; u < 8; ++u) X[u * 8 + r0][n] = y[u];
        __syncthreads();
    }
}

// Z = Linv^T * X in place (block-triangular transpose, 2 column passes).
__device__ __forceinline__ void apply_trans_128(const float (*A)[DD + 1],
                                                float (*X)[XS], int tid) {
    const int nb = tid & 15, r0 = tid >> 4;
#pragma unroll 1
    for (int pass = 0; pass < 2; ++pass) {
        const int n = nb + 16 * pass;
        float y[8];
#pragma unroll
        for (int u = 0; u < 8; ++u) y[u] = 0.f;
#pragma unroll
        for (int kb = 0; kb < 8; ++kb) {
#pragma unroll
            for (int q = 0; q < 8; ++q) {           // dense blocks u < kb
                const int k = kb * 8 + q;
                const float xk = X[k][n];
#pragma unroll
                for (int u = 0; u < kb; ++u)
                    y[u] += A[k][u * 8 + r0] * xk;
            }
            for (int q = r0; q < 8; ++q)            // diag block, q >= r0
                y[kb] += A[kb * 8 + q][kb * 8 + r0] * X[kb * 8 + q][n];
        }
        __syncthreads();
#pragma unroll
        for (int u = 0; u < 8; ++u) X[u * 8 + r0][n] = y[u];
        __syncthreads();
    }
}

// ============ Phase 2: B_q path -> R = W^T Q W  (per batch) ============
__global__ __launch_bounds__(TT, 7) void rbf_phase2(
    const float* __restrict__ mean, const float* __restrict__ cov,
    const float* __restrict__ centers, const float* __restrict__ weights,
    const float* __restrict__ ls) {
    __shared__ float A[DD][DD + 1];
    __shared__ __align__(8) float X[DD][XS];
    __shared__ float G[NC][NC + 1];     // U scratch -> Gram -> Q
    __shared__ float W[NC][AA];
    __shared__ float pw[NC][AA];        // P = Q W
    __shared__ float smean[DD], sl2[DD], ldiag[DD];
    __shared__ float gd[NC];
    __shared__ float s_cq[1];

    const int tid = threadIdx.x;
    const int b = blockIdx.x;
    const float* covb = cov + (size_t)b * DD * DD;
    const float* meanb = mean + (size_t)b * DD;
    float* U = &G[0][0];

    if (tid < DD) {
        float l = ls[tid];
        smean[tid] = meanb[tid];
        sl2[tid] = l * l;
    }
#pragma unroll
    for (int h = 0; h < 2; ++h) {
        int e = tid + TT * h;
        W[e >> 3][e & 7] = weights[e];
    }
    __syncthreads();

    for (int idx = tid; idx < DD * DD; idx += TT) {
        int i = idx >> 6, j = idx & 63;
        float v = covb[idx];
        if (i == j) v += 0.5f * sl2[i];
        A[i][j] = v;
    }
    for (int idx = tid; idx < NC * DD; idx += TT) {
        int nn = idx >> 6, d = idx & 63;
        X[d][nn] = centers[idx] - smean[d];
    }
    __syncthreads();

    cholesky64_128(A, tid);
    if (tid < DD) ldiag[tid] = 0.5f * logf(0.5f * sl2[tid]) - logf(A[tid][tid]);
    __syncthreads();
    if (tid < 32) {
        float s = ldiag[tid] + ldiag[tid + 32];
#pragma unroll
        for (int o = 16; o > 0; o >>= 1) s += __shfl_down_sync(0xffffffffu, s, o);
        if (tid == 0) s_cq[0] = expf(s);   // c_q
    }
    invert_lower64_128(A, U, tid);
    apply_fwd_128(A, X, 0, tid);           // Y = Linv_q * D

    // G = Y^T Y, 2x2 register tile, float2 loads, two n-halves
    {
        const int m2 = tid & 15, n2b = tid >> 4;
#pragma unroll 1
        for (int nh = 0; nh < 2; ++nh) {
            const int n0 = 2 * (n2b + 8 * nh), m0 = 2 * m2;
            float g00 = 0.f, g01 = 0.f, g10 = 0.f, g11 = 0.f;
            for (int d = 0; d < DD; ++d) {
                float2 a2 = *(const float2*)&X[d][n0];
                float2 b2 = *(const float2*)&X[d][m0];
                g00 += a2.x * b2.x; g01 += a2.x * b2.y;
                g10 += a2.y * b2.x; g11 += a2.y * b2.y;
            }
            G[n0][m0] = g00; G[n0][m0 + 1] = g01;
            G[n0 + 1][m0] = g10; G[n0 + 1][m0 + 1] = g11;
        }
    }
    __syncthreads();
    if (tid < NC) gd[tid] = G[tid][tid];
    __syncthreads();
    // Q = c_q * exp(exp1 - (G_nn + 2G_nm + G_mm)/8)  (hot path: __expf ok)
    {
        float cq = s_cq[0];
        for (int p = tid; p < NC * NC; p += TT) {
            int nn = p >> 5, m = p & 31;
            G[nn][m] = cq * __expf(g_exp1[p] - 0.125f * (gd[nn] + 2.0f * G[nn][m] + gd[m]));
        }
    }
    __syncthreads();
    // P = Q W  (two nn-halves)
#pragma unroll 1
    for (int h = 0; h < 2; ++h) {
        int nn = (tid >> 3) + 16 * h, c2 = tid & 7;
        float acc = 0.f;
#pragma unroll 8
        for (int m = 0; m < NC; ++m) acc += G[nn][m] * W[m][c2];
        pw[nn][c2] = acc;
    }
    __syncthreads();
    // R = W^T P  -> global handoff
    if (tid < AA * AA) {
        int a = tid >> 3, c2 = tid & 7;
        float acc = 0.f;
        for (int nn = 0; nn < NC; ++nn) acc += W[nn][a] * pw[nn][c2];
        gRbuf[(size_t)b * 64 + tid] = acc;
    }
}

// ===== Phase 1: B_mat path -> phi, CC, am; combine with R -> outputs =====
__global__ __launch_bounds__(TT, 7) void rbf_phase1(
    const float* __restrict__ mean, const float* __restrict__ cov,
    const float* __restrict__ centers, const float* __restrict__ weights,
    const float* __restrict__ ls,
    float* __restrict__ out_am, float* __restrict__ out_ac,
    float* __restrict__ out_cc) {
    __shared__ float A[DD][DD + 1];
    __shared__ __align__(8) float X[DD][XS];
    __shared__ float scratch[816];      // U (816) | CC (512) + cp (256)
    __shared__ float W[NC][AA];
    __shared__ float pw[NC][AA];
    __shared__ float phi[NC];
    __shared__ float smean[DD], sinvl[DD], ldiag[DD];
    __shared__ float s_scal[1];
    __shared__ float s_am[AA], s_dc[AA], s_cd[AA];
    __shared__ float R8[AA][AA + 1];
    __shared__ float ACm[AA][AA + 1];

    const int tid = threadIdx.x;
    const int b = blockIdx.x;
    const float* covb = cov + (size_t)b * DD * DD;
    const float* meanb = mean + (size_t)b * DD;
    float* CCp = scratch;               // 512 floats (after U is dead)
    float* cpb = scratch + 512;         // 256 floats

    if (tid < DD) {
        float l = ls[tid];
        smean[tid] = meanb[tid];
        sinvl[tid] = 1.0f / l;
    }
#pragma unroll
    for (int h = 0; h < 2; ++h) {
        int e = tid + TT * h;
        W[e >> 3][e & 7] = weights[e];
    }
    __syncthreads();

    // A = diag(invl) cov diag(invl) + I ; X = scaled diffs
    for (int idx = tid; idx < DD * DD; idx += TT) {
        int i = idx >> 6, j = idx & 63;
        float v = covb[idx] * sinvl[i] * sinvl[j];
        if (i == j) v += 1.0f;
        A[i][j] = v;
    }
    for (int idx = tid; idx < NC * DD; idx += TT) {
        int nn = idx >> 6, d = idx & 63;
        X[d][nn] = (centers[idx] - smean[d]) * sinvl[d];
    }
    __syncthreads();

    cholesky64_128(A, tid);
    if (tid < DD) ldiag[tid] = logf(A[tid][tid]);
    __syncthreads();
    if (tid < 32) {
        float s = ldiag[tid] + ldiag[tid + 32];
#pragma unroll
        for (int o = 16; o > 0; o >>= 1) s += __shfl_down_sync(0xffffffffu, s, o);
        if (tid == 0) s_scal[0] = expf(-s);   // exp(-0.5*logdet)
    }
    invert_lower64_128(A, scratch, tid);
    apply_fwd_128(A, X, cpb, tid);        // Y1 = Linv*S, colnorms -> cpb
    apply_trans_128(A, X, tid);           // T = Linv^T * Y1

    // phi[n] = normalizer * exp(-0.5 |Y1 col n|^2)  (accurate expf: tiny vals)
    if (tid < NC) {
        float acc = 0.f;
#pragma unroll
        for (int u = 0; u < 8; ++u) acc += cpb[u * 32 + tid];
        phi[tid] = expf(-0.5f * acc) * s_scal[0];
    }
    __syncthreads();
#pragma unroll
    for (int h = 0; h < 2; ++h) {
        int e = tid + TT * h;
        pw[e >> 3][e & 7] = phi[e >> 3] * W[e >> 3][e & 7];
    }
    __syncthreads();
    if (tid < AA) {
        float s = 0.f;
        for (int nn = 0; nn < NC; ++nn) s += pw[nn][tid];
        s_am[tid] = s;
    }
    // CC[d][a] = invl[d] * sum_n T[d][n] (phi W)[n][a]
    for (int idx = tid; idx < DD * AA; idx += TT) {
        int d = idx >> 3, a = idx & 7;
        float acc = 0.f;
#pragma unroll 8
        for (int nn = 0; nn < NC; ++nn) acc += X[d][nn] * pw[nn][a];
        CCp[idx] = acc * sinvl[d];
    }
    // pull R from phase 2
    if (tid < AA * AA) R8[tid >> 3][tid & 7] = gRbuf[(size_t)b * 64 + tid];
    __syncthreads();
    if (tid < AA * AA) {
        int a = tid >> 3, c = tid & 7;
        float v = 0.5f * (R8[a][c] + R8[c][a]) - s_am[a] * s_am[c];
        if (a == c) v += 1e-6f;
        ACm[a][c] = v;
    }
    __syncthreads();

    // squash_sin (max_action = 1) — accurate libm (values can be ~1e-15;
    // sin.approx flushes tiny args to 0: the exact-1.0 failure of R7/R10)
    if (tid < AA) {
        float dc = ACm[tid][tid];
        float e = expf(-0.5f * dc);
        s_dc[tid] = dc;
        s_cd[tid] = e * cosf(s_am[tid]);
        out_am[(size_t)b * AA + tid] = e * sinf(s_am[tid]);
    }
    __syncthreads();
    if (tid < AA * AA) {
        int a = tid >> 3, c = tid & 7;
        float lq = -0.5f * (s_dc[a] + s_dc[c]);
        float q = expf(lq);
        float v = ACm[a][c];
        float sq = 0.5f * ((expf(lq + v) - q) * cosf(s_am[a] - s_am[c])
                         - (expf(lq - v) - q) * cosf(s_am[a] + s_am[c]));
        out_ac[(size_t)b * AA * AA + tid] = sq;
    }
    for (int idx = tid; idx < DD * AA; idx += TT) {
        out_cc[(size_t)b * DD * AA + idx] = CCp[idx] * s_cd[idx & 7];
    }
}

extern "C" void kernel_launch(void* const* d_in, const int* in_sizes, int n_in,
                              void* d_out, int out_size) {
    const float* mean = (const float*)d_in[0];
    const float* cov = (const float*)d_in[1];
    const float* centers = (const float*)d_in[2];
    const float* weights = (const float*)d_in[3];
    const float* ls = (const float*)d_in[4];
    float* out = (float*)d_out;

    int B = in_sizes[0] / DD;   // 2048
    float* out_am = out;
    float* out_ac = out + (size_t)B * AA;
    float* out_cc = out + (size_t)B * AA + (size_t)B * AA * AA;

    prep_kernel<<<1, 1024>>>(centers, ls);
    rbf_phase2<<<B, TT>>>(mean, cov, centers, weights, ls);
    rbf_phase1<<<B, TT>>>(mean, cov, centers, weights, ls, out_am, out_ac, out_cc);
}